// round 1
// baseline (speedup 1.0000x reference)
#include <cuda_runtime.h>
#include <cuda_bf16.h>
#include <cstddef>

// ---------------- problem constants ----------------
#define BATCH   16
#define LTOT    2048
#define DIMX    128
#define DIN     256          // D_INNER
#define DST     16           // D_STATE
#define MTOK    (BATCH*LTOT) // 32768 tokens

// ---------------- scratch layout (floats) ----------------
#define OFF_X0   0UL
#define OFF_X1   4194304UL
#define OFF_XN   8388608UL
#define OFF_XZ   12582912UL   // (M,512): cols 0..255 = xc, 256..511 = z
#define OFF_U0   29360128UL   // (M,256)
#define OFF_U1   37748736UL
#define OFF_XD0  46137344UL   // (M,64) padded xdbl
#define OFF_XD1  48234496UL
#define OFF_DT0  50331648UL   // (M,256)
#define OFF_DT1  58720256UL
#define OFF_Y0   67108864UL   // gated y, (M,256)
#define OFF_Y1   75497472UL
#define OFF_WXP  83886080UL   // 2 x (64,256) padded Wx
#define TOT_F    83918848UL

__device__ __align__(16) float g_buf[TOT_F];

__device__ __forceinline__ float siluf(float x) { return x / (1.f + __expf(-x)); }

// ---------------- concat x = [x_adap ; xi_adap] along L ----------------
__global__ void concat_kernel(const float* __restrict__ xa, const float* __restrict__ xi,
                              float* __restrict__ x0) {
    int i = blockIdx.x * 256 + threadIdx.x;       // 16384 blocks
    int c = i & 127;
    int t = (i >> 7) & 2047;
    int b = i >> 18;
    float v = (t < 1024) ? xa[((size_t)b*1024 + t)*128 + c]
                         : xi[((size_t)b*1024 + (t-1024))*128 + c];
    x0[i] = v;
}

// ---------------- pad Wx (2,40,256) -> (2,64,256) ----------------
__global__ void padwx_kernel(const float* __restrict__ Wx, float* __restrict__ wxp) {
    int i = blockIdx.x * 256 + threadIdx.x;       // 128 blocks -> 32768
    int k = i & 255;
    int e = (i >> 8) & 63;
    int l = i >> 14;
    wxp[i] = (e < 40) ? Wx[((size_t)l*40 + e)*256 + k] : 0.f;
}

// ---------------- LayerNorm over DIM=128 ----------------
__global__ void ln_kernel(const float* __restrict__ x, const float* __restrict__ w,
                          const float* __restrict__ b, float* __restrict__ out) {
    __shared__ float red[4];
    int tok = blockIdx.x;
    int c = threadIdx.x;
    size_t idx = (size_t)tok*128 + c;
    float v = x[idx];
    float s = v;
    #pragma unroll
    for (int o = 16; o; o >>= 1) s += __shfl_xor_sync(0xffffffffu, s, o);
    if ((c & 31) == 0) red[c >> 5] = s;
    __syncthreads();
    float mu = (red[0] + red[1] + red[2] + red[3]) * 0.0078125f;
    __syncthreads();
    float d = v - mu;
    float sq = d * d;
    #pragma unroll
    for (int o = 16; o; o >>= 1) sq += __shfl_xor_sync(0xffffffffu, sq, o);
    if ((c & 31) == 0) red[c >> 5] = sq;
    __syncthreads();
    float var = (red[0] + red[1] + red[2] + red[3]) * 0.0078125f;
    out[idx] = d * rsqrtf(var + 1e-5f) * w[c] + b[c];
}

// ---------------- generic fp32 GEMM: C(M,N) = (A [+A2]) (M,K) * W(N,K)^T [+ rscale*resid] ----
// BM=128, BN=64, BK=16, 256 threads, 8x4 micro-tile
#define BM 128
#define BN 64
#define BK 16

__global__ __launch_bounds__(256)
void gemm_kernel(const float* __restrict__ A, const float* __restrict__ A2,
                 const float* __restrict__ W, int N, int K,
                 const float* __restrict__ resid, float rscale,
                 float* __restrict__ C) {
    __shared__ float As[BK][BM + 4];
    __shared__ float Ws[BK][BN + 4];
    int m_block = blockIdx.x * BM;
    int n_block = blockIdx.y * BN;
    int tid = threadIdx.x;
    int tr = tid >> 4, tc = tid & 15;
    int m0 = tr * 8, n0 = tc * 4;
    int la_r = tid >> 2;            // 0..63
    int la_c = (tid & 3) * 4;       // 0,4,8,12

    float acc[8][4];
    #pragma unroll
    for (int i = 0; i < 8; i++)
        #pragma unroll
        for (int j = 0; j < 4; j++) acc[i][j] = 0.f;

    for (int kt = 0; kt < K; kt += BK) {
        #pragma unroll
        for (int rr = 0; rr < 2; rr++) {
            int r = la_r + rr * 64;
            const float* ap = A + (size_t)(m_block + r)*K + kt + la_c;
            float4 v = *(const float4*)ap;
            if (A2) {
                float4 v2 = *(const float4*)(A2 + (size_t)(m_block + r)*K + kt + la_c);
                v.x += v2.x; v.y += v2.y; v.z += v2.z; v.w += v2.w;
            }
            As[la_c + 0][r] = v.x; As[la_c + 1][r] = v.y;
            As[la_c + 2][r] = v.z; As[la_c + 3][r] = v.w;
        }
        {
            const float* wp = W + (size_t)(n_block + la_r)*K + kt + la_c;
            float4 v = *(const float4*)wp;
            Ws[la_c + 0][la_r] = v.x; Ws[la_c + 1][la_r] = v.y;
            Ws[la_c + 2][la_r] = v.z; Ws[la_c + 3][la_r] = v.w;
        }
        __syncthreads();
        #pragma unroll
        for (int k = 0; k < BK; k++) {
            float a[8], bb[4];
            *(float4*)&a[0] = *(const float4*)&As[k][m0];
            *(float4*)&a[4] = *(const float4*)&As[k][m0 + 4];
            *(float4*)&bb[0] = *(const float4*)&Ws[k][n0];
            #pragma unroll
            for (int i = 0; i < 8; i++)
                #pragma unroll
                for (int j = 0; j < 4; j++) acc[i][j] += a[i] * bb[j];
        }
        __syncthreads();
    }

    #pragma unroll
    for (int i = 0; i < 8; i++) {
        int m = m_block + m0 + i;
        #pragma unroll
        for (int j = 0; j < 4; j++) {
            int n = n_block + n0 + j;
            float v = acc[i][j];
            if (resid) v += rscale * resid[(size_t)m*N + n];
            C[(size_t)m*N + n] = v;
        }
    }
}

// ---------------- causal + anti-causal conv(4) + silu ----------------
__global__ void conv_kernel(const float* __restrict__ xz,
                            const float* __restrict__ convw, const float* __restrict__ convb,
                            float* __restrict__ uf, float* __restrict__ ub) {
    int bt = blockIdx.x;            // 0..32767
    int d = threadIdx.x;            // 0..255
    int t = bt & 2047;
    const float* base = xz + (size_t)bt*512 + d;
    float w0 = convw[d*4+0], w1 = convw[d*4+1], w2 = convw[d*4+2], w3 = convw[d*4+3];
    float cb = convb[d];
    float v0  = base[0];
    float vm1 = (t >= 1)    ? base[-512]  : 0.f;
    float vm2 = (t >= 2)    ? base[-1024] : 0.f;
    float vm3 = (t >= 3)    ? base[-1536] : 0.f;
    float vp1 = (t <= 2046) ? base[512]   : 0.f;
    float vp2 = (t <= 2045) ? base[1024]  : 0.f;
    float vp3 = (t <= 2044) ? base[1536]  : 0.f;
    float f = cb + vm3*w0 + vm2*w1 + vm1*w2 + v0*w3;
    float r = cb + vp3*w0 + vp2*w1 + vp1*w2 + v0*w3;
    uf[(size_t)bt*256 + d] = siluf(f);
    ub[(size_t)bt*256 + d] = siluf(r);
}

// ---------------- dt = softplus(xdbl[:,:8] @ Wdt^T + bdt), both dirs ----------------
__global__ void dt_kernel(const float* __restrict__ xd0, const float* __restrict__ xd1,
                          const float* __restrict__ Wdt, const float* __restrict__ bdt,
                          float* __restrict__ dt0, float* __restrict__ dt1) {
    int tok = blockIdx.x;
    int d = threadIdx.x;
    float w[8];
    #pragma unroll
    for (int j = 0; j < 8; j++) w[j] = Wdt[(size_t)d*8 + j];
    float bb = bdt[d];
    #pragma unroll
    for (int dir = 0; dir < 2; dir++) {
        const float* r = (dir ? xd1 : xd0) + (size_t)tok*64;
        float acc = bb;
        #pragma unroll
        for (int j = 0; j < 8; j++) acc += r[j] * w[j];
        float sp = (acc > 20.f) ? acc : log1pf(__expf(acc));
        (dir ? dt1 : dt0)[(size_t)tok*256 + d] = sp;
    }
}

// ---------------- selective scan (both directions), gated output ----------------
// 4 lanes per (b,d) channel, 4 states each; 1024 warps total.
__global__ __launch_bounds__(256)
void scan_kernel(const float* __restrict__ A_log, const float* __restrict__ Dp,
                 const float* __restrict__ u0, const float* __restrict__ u1,
                 const float* __restrict__ dt0, const float* __restrict__ dt1,
                 const float* __restrict__ xd0, const float* __restrict__ xd1,
                 const float* __restrict__ xz,
                 float* __restrict__ y0, float* __restrict__ y1) {
    int wglob = blockIdx.x * 8 + (threadIdx.x >> 5);
    int lane = threadIdx.x & 31;
    int dir = wglob >> 9;
    int rem = wglob & 511;
    int b = rem >> 5;
    int d0 = (rem & 31) << 3;
    int ch = lane >> 2, sg = lane & 3;
    int d = d0 + ch, s0 = sg * 4;

    const float* u  = dir ? u1 : u0;
    const float* dtp = dir ? dt1 : dt0;
    const float* xd = dir ? xd1 : xd0;
    float* y = dir ? y1 : y0;

    float a0 = -__expf(A_log[(size_t)d*16 + s0 + 0]);
    float a1 = -__expf(A_log[(size_t)d*16 + s0 + 1]);
    float a2 = -__expf(A_log[(size_t)d*16 + s0 + 2]);
    float a3 = -__expf(A_log[(size_t)d*16 + s0 + 3]);
    float dpd = Dp[d];

    long tok0 = (long)b*2048 + (dir ? 2047 : 0);
    long stp = dir ? -1 : 1;
    const float* pu = u + tok0*256 + d;
    const float* pdt = dtp + tok0*256 + d;
    const float* pxd = xd + tok0*64;
    const float* pz = xz + tok0*512 + 256 + d;
    float* py = y + tok0*256 + d;
    long su = stp*256, sxd = stp*64, sz = stp*512;

    float h0 = 0.f, h1 = 0.f, h2 = 0.f, h3 = 0.f;

    float dtv = *pdt, uv = *pu;
    float4 Bv = *(const float4*)(pxd + 8 + s0);
    float4 Cv = *(const float4*)(pxd + 24 + s0);

    #pragma unroll 4
    for (int t = 0; t < 2048; t++) {
        float ndt = 0.f, nuv = 0.f;
        float4 nB = make_float4(0,0,0,0), nC = make_float4(0,0,0,0);
        if (t < 2047) {
            ndt = pdt[su];
            nuv = pu[su];
            nB = *(const float4*)(pxd + sxd + 8 + s0);
            nC = *(const float4*)(pxd + sxd + 24 + s0);
        }
        float xb = dtv * uv;
        h0 = __expf(dtv * a0) * h0 + xb * Bv.x;
        h1 = __expf(dtv * a1) * h1 + xb * Bv.y;
        h2 = __expf(dtv * a2) * h2 + xb * Bv.z;
        h3 = __expf(dtv * a3) * h3 + xb * Bv.w;
        float part = h0*Cv.x + h1*Cv.y + h2*Cv.z + h3*Cv.w;
        part += __shfl_xor_sync(0xffffffffu, part, 1);
        part += __shfl_xor_sync(0xffffffffu, part, 2);
        if (sg == 0) {
            float zv = *pz;
            float yv = part + uv * dpd;
            *py = yv * (zv / (1.f + __expf(-zv)));
        }
        pdt += su; pu += su; pxd += sxd; pz += sz; py += su;
        dtv = ndt; uv = nuv; Bv = nB; Cv = nC;
    }
}

// ---------------- launcher ----------------
extern "C" void kernel_launch(void* const* d_in, const int* in_sizes, int n_in,
                              void* d_out, int out_size) {
    const float* x_adap  = (const float*)d_in[0];
    const float* xi_adap = (const float*)d_in[1];
    const float* ln_w    = (const float*)d_in[2];
    const float* ln_b    = (const float*)d_in[3];
    const float* Win     = (const float*)d_in[4];
    const float* convw   = (const float*)d_in[5];
    const float* convb   = (const float*)d_in[6];
    const float* Wx      = (const float*)d_in[7];
    const float* Wdt     = (const float*)d_in[8];
    const float* bdt     = (const float*)d_in[9];
    const float* A_log   = (const float*)d_in[10];
    const float* Dp      = (const float*)d_in[11];
    const float* Wout    = (const float*)d_in[12];
    float* out = (float*)d_out;

    float* g = nullptr;
    cudaGetSymbolAddress((void**)&g, g_buf);
    float* x0  = g + OFF_X0;
    float* x1  = g + OFF_X1;
    float* xn  = g + OFF_XN;
    float* xz  = g + OFF_XZ;
    float* u0  = g + OFF_U0;
    float* u1  = g + OFF_U1;
    float* xd0 = g + OFF_XD0;
    float* xd1 = g + OFF_XD1;
    float* db0 = g + OFF_DT0;
    float* db1 = g + OFF_DT1;
    float* y0  = g + OFF_Y0;
    float* y1  = g + OFF_Y1;
    float* wxp = g + OFF_WXP;

    concat_kernel<<<16384, 256>>>(x_adap, xi_adap, x0);
    padwx_kernel<<<128, 256>>>(Wx, wxp);

    for (int i = 0; i < 2; i++) {
        const float* xin = i ? x1 : x0;
        float* xout = i ? out : x1;

        ln_kernel<<<MTOK, 128>>>(xin, ln_w + i*128, ln_b + i*128, xn);

        // xz = LN(x) @ Win^T  (M,512)
        gemm_kernel<<<dim3(MTOK/BM, 512/BN), 256>>>(
            xn, nullptr, Win + (size_t)i*512*128, 512, 128, nullptr, 0.f, xz);

        conv_kernel<<<MTOK, 256>>>(xz, convw + (size_t)i*256*4, convb + i*256, u0, u1);

        // xdbl = u @ WxPad^T  (M,64) per direction
        gemm_kernel<<<dim3(MTOK/BM, 1), 256>>>(
            u0, nullptr, wxp + (size_t)i*64*256, 64, 256, nullptr, 0.f, xd0);
        gemm_kernel<<<dim3(MTOK/BM, 1), 256>>>(
            u1, nullptr, wxp + (size_t)i*64*256, 64, 256, nullptr, 0.f, xd1);

        dt_kernel<<<MTOK, 256>>>(xd0, xd1, Wdt + (size_t)i*256*8, bdt + i*256, db0, db1);

        scan_kernel<<<128, 256>>>(A_log + (size_t)i*256*16, Dp + i*256,
                                  u0, u1, db0, db1, xd0, xd1, xz, y0, y1);

        // x_next = 2*x + (y0+y1) @ Wout^T
        gemm_kernel<<<dim3(MTOK/BM, 128/BN), 256>>>(
            y0, y1, Wout + (size_t)i*128*256, 128, 256, xin, 2.0f, xout);
    }
}